// round 11
// baseline (speedup 1.0000x reference)
#include <cuda_runtime.h>

typedef unsigned long long ull;

// Weight tables, each tap as quad (c, s, s, c):
//   ffma2(S, A, quad.lo): (vc*wc, vs*ws) -> Sx = lo+hi
//   ffma2(T, A, quad.hi): (vc*ws, vs*wc) -> Sy = hi-lo
__device__ __align__(16) float4 g_w1q[16];     // [co*4 + tap]
__device__ __align__(16) float4 g_w2q[520];    // [co*65 + c*16 + i*4 + j]
__device__ __align__(16) float4 g_wfq[2880];   // [o*288 + f]

__global__ void prep_kernel(const float* __restrict__ w1,
                            const float* __restrict__ w2,
                            const float* __restrict__ wf) {
    int gt = blockIdx.x * blockDim.x + threadIdx.x;
    for (int i = gt; i < 3408; i += gridDim.x * blockDim.x) {
        if (i < 16) {
            float s, c; sincosf(w1[i], &s, &c);
            g_w1q[i] = make_float4(c, s, s, c);
        } else if (i < 528) {
            int k = i - 16;
            int co = k >> 6, r = k & 63;
            float s, c; sincosf(w2[k], &s, &c);
            g_w2q[co * 65 + r] = make_float4(c, s, s, c);
        } else {
            int k = i - 528;
            int f = k / 10, o = k % 10;
            float s, c; sincosf(wf[k], &s, &c);
            g_wfq[o * 288 + f] = make_float4(c, s, s, c);
        }
    }
}

// packed dual-FMA: acc(lo,hi) += a(lo,hi) * b(lo,hi)
static __device__ __forceinline__ void ffma2(ull& acc, ull a, ull b) {
    asm("fma.rn.f32x2 %0, %1, %2, %0;" : "+l"(acc) : "l"(a), "l"(b));
}
static __device__ __forceinline__ float f2lo(ull v) { return __uint_as_float((unsigned)v); }
static __device__ __forceinline__ float f2hi(ull v) { return __uint_as_float((unsigned)(v >> 32)); }
static __device__ __forceinline__ ull pack2(float lo, float hi) {
    ull r;
    asm("mov.b64 %0, {%1, %2};" : "=l"(r) : "f"(lo), "f"(hi));
    return r;
}

// MUFU-free sincos: quadrant reduction + minimax polys
static __device__ __forceinline__ void fast_sincos(float x, float& s, float& c) {
    float t = fmaf(x, 0.63661977236758134f, 12582912.0f);
    unsigned q = __float_as_uint(t);
    float kf = t - 12582912.0f;
    float r = fmaf(kf, -1.57079625129699707031f, x);
    r = fmaf(kf, -7.54978941586159e-08f, r);
    float y = r * r;
    float ps = fmaf(y, -1.95152959e-4f, 8.33216087e-3f);
    ps = fmaf(y, ps, -1.66666546e-1f);
    float s0 = fmaf(r * y, ps, r);
    float pc = fmaf(y, 2.44331571e-5f, -1.38873162e-3f);
    pc = fmaf(y, pc, 4.16666232e-2f);
    pc = fmaf(y, pc, -0.5f);
    float c0 = fmaf(y, pc, 1.0f);
    bool sw = q & 1u;
    float ss = sw ? c0 : s0;
    float cc = sw ? s0 : c0;
    unsigned sgs = (q & 2u) << 30;
    unsigned sgc = ((q + 1u) & 2u) << 30;
    s = __uint_as_float(__float_as_uint(ss) ^ sgs);
    c = __uint_as_float(__float_as_uint(cc) ^ sgc);
}

// MUFU-free rsqrt
static __device__ __forceinline__ float fast_rsqrt(float d) {
    float y = __uint_as_float(0x5F3759DFu - (__float_as_uint(d) >> 1));
    float h = 0.5f * d;
    y = y * fmaf(-(h * y), y, 1.5f);
    y = y * fmaf(-(h * y), y, 1.5f);
    return y;
}

// Two images per block. h1 interleaved float2 [c*196 + row*14 + pos] per image.
__global__ __launch_bounds__(320, 4) void ring_kernel(const float* __restrict__ x,
                                                      float* __restrict__ out) {
    __shared__ __align__(16) float2 s_h1[2][784];
    __shared__ __align__(16) float2 s_h2[2][288];   // [(ho*6+wo)*8 + co]
    __shared__ __align__(16) float4 s_w2[520];      // quad [co*65 + c*16+i*4+j]

    const int tid = threadIdx.x;
    const size_t i0 = (size_t)blockIdx.x * 2;

    // ---- w2 staging (consumed after the barrier below) ----
    for (int i = tid; i < 520; i += 320) s_w2[i] = g_w2q[i];

    // ---- Fused stage 0+1: conv1 2x2 s2 for BOTH images (392 jobs) ----
    for (int p = tid; p < 392; p += 320) {
        int img = p >= 196;
        int pos = p - 196 * img;
        int py = pos / 14, px = pos % 14;
        const float* xb = x + (i0 + img) * 784 + py * 56 + px * 2;
        float2 p0 = *reinterpret_cast<const float2*>(xb);
        float2 p1 = *reinterpret_cast<const float2*>(xb + 28);
        float c00, s00, c01, s01, c10, s10, c11, s11;
        fast_sincos(p0.x, s00, c00);
        fast_sincos(p0.y, s01, c01);
        fast_sincos(p1.x, s10, c10);
        fast_sincos(p1.y, s11, c11);
        ull A0 = pack2(c00, s00), A1 = pack2(c01, s01);
        ull A2 = pack2(c10, s10), A3 = pack2(c11, s11);
        int dst = py * 14 + px;
        const ulonglong2* w1 = reinterpret_cast<const ulonglong2*>(g_w1q);
#pragma unroll
        for (int co = 0; co < 4; co++) {
            ulonglong2 q0 = __ldg(w1 + co * 4 + 0);
            ulonglong2 q1 = __ldg(w1 + co * 4 + 1);
            ulonglong2 q2 = __ldg(w1 + co * 4 + 2);
            ulonglong2 q3 = __ldg(w1 + co * 4 + 3);
            ull S = 0, T = 0;
            ffma2(S, A0, q0.x); ffma2(T, A0, q0.y);
            ffma2(S, A1, q1.x); ffma2(T, A1, q1.y);
            ffma2(S, A2, q2.x); ffma2(T, A2, q2.y);
            ffma2(S, A3, q3.x); ffma2(T, A3, q3.y);
            float Sx = f2lo(S) + f2hi(S);
            float Sy = f2hi(T) - f2lo(T);
            float r = fast_rsqrt(fmaxf(Sx * Sx + Sy * Sy, 1e-30f));
            s_h1[img][co * 196 + dst] = make_float2(Sx * r, Sy * r);
        }
    }
    __syncthreads();

    // ---- Stage 2: conv2 4x4 s2 -> 288 outputs/img, 2 imgs, 2 out/thread ----
    int st = tid + ((blockIdx.x & 3) << 5);    // rotate idle warp across SMSPs
    if (st >= 320) st -= 320;
    if (st < 288) {
        int img = st >= 144;
        int t = st - 144 * img;
        int co = t & 7, q = t >> 3;            // q in [0,18): ho = q/3, wp = q%3
        int ho = q / 3, wp = q % 3;            // outputs wo = 2wp, 2wp+1
        const float2* h1 = s_h1[img];
        const int vb0 = ho * 28 + wp * 4;      // float2 index, even -> 16B aligned
        const int wb0 = co * 65;
        ull SA = 0, TA = 0, SB = 0, TB = 0;
#pragma unroll
        for (int c = 0; c < 4; c++) {
#pragma unroll
            for (int i = 0; i < 4; i++) {
                int vb = c * 196 + vb0 + i * 14;
                ulonglong2 a01 = *(const ulonglong2*)&h1[vb];
                ulonglong2 a23 = *(const ulonglong2*)&h1[vb + 2];
                ulonglong2 a45 = *(const ulonglong2*)&h1[vb + 4];
                const ulonglong2* w = (const ulonglong2*)&s_w2[wb0 + c * 16 + i * 4];
                ulonglong2 q0 = w[0], q1 = w[1], q2 = w[2], q3 = w[3];
                // output A: taps j=0..3
                ffma2(SA, a01.x, q0.x); ffma2(TA, a01.x, q0.y);
                ffma2(SA, a01.y, q1.x); ffma2(TA, a01.y, q1.y);
                ffma2(SA, a23.x, q2.x); ffma2(TA, a23.x, q2.y);
                ffma2(SA, a23.y, q3.x); ffma2(TA, a23.y, q3.y);
                // output B: taps j=2..5 against w j=0..3
                ffma2(SB, a23.x, q0.x); ffma2(TB, a23.x, q0.y);
                ffma2(SB, a23.y, q1.x); ffma2(TB, a23.y, q1.y);
                ffma2(SB, a45.x, q2.x); ffma2(TB, a45.x, q2.y);
                ffma2(SB, a45.y, q3.x); ffma2(TB, a45.y, q3.y);
            }
        }
        int d0 = (ho * 6 + 2 * wp) * 8 + co;
        {
            float Sx = f2lo(SA) + f2hi(SA);
            float Sy = f2hi(TA) - f2lo(TA);
            float r = fast_rsqrt(fmaxf(Sx * Sx + Sy * Sy, 1e-30f));
            s_h2[img][d0] = make_float2(Sx * r, Sy * r);
        }
        {
            float Sx = f2lo(SB) + f2hi(SB);
            float Sy = f2hi(TB) - f2lo(TB);
            float r = fast_rsqrt(fmaxf(Sx * Sx + Sy * Sy, 1e-30f));
            s_h2[img][d0 + 8] = make_float2(Sx * r, Sy * r);
        }
    }
    __syncthreads();

    // ---- Stage 3: FF ring; warp = class o, both images interleaved (2x ILP) ----
    int o = tid >> 5, lane = tid & 31;
    const ulonglong2* wfo = reinterpret_cast<const ulonglong2*>(g_wfq + o * 288);
    ull S0 = 0, T0 = 0, S1 = 0, T1 = 0;
#pragma unroll
    for (int f = lane, k = 0; k < 9; k++, f += 32) {
        ulonglong2 w = __ldg(wfo + f);
        ull a0 = *(const ull*)&s_h2[0][f];
        ull a1 = *(const ull*)&s_h2[1][f];
        ffma2(S0, a0, w.x); ffma2(T0, a0, w.y);
        ffma2(S1, a1, w.x); ffma2(T1, a1, w.y);
    }
    float Sx0 = f2lo(S0) + f2hi(S0), Sy0 = f2hi(T0) - f2lo(T0);
    float Sx1 = f2lo(S1) + f2hi(S1), Sy1 = f2hi(T1) - f2lo(T1);
#pragma unroll
    for (int off = 16; off; off >>= 1) {
        Sx0 += __shfl_xor_sync(0xffffffff, Sx0, off);
        Sy0 += __shfl_xor_sync(0xffffffff, Sy0, off);
        Sx1 += __shfl_xor_sync(0xffffffff, Sx1, off);
        Sy1 += __shfl_xor_sync(0xffffffff, Sy1, off);
    }
    if (lane == 0) {
        out[i0 * 10 + o]      = Sy0 * fast_rsqrt(fmaxf(Sx0 * Sx0 + Sy0 * Sy0, 1e-30f));
        out[(i0 + 1) * 10 + o] = Sy1 * fast_rsqrt(fmaxf(Sx1 * Sx1 + Sy1 * Sy1, 1e-30f));
    }
}

extern "C" void kernel_launch(void* const* d_in, const int* in_sizes, int n_in,
                              void* d_out, int out_size) {
    const float* x  = (const float*)d_in[0];
    const float* w1 = (const float*)d_in[1];
    const float* w2 = (const float*)d_in[2];
    const float* wf = (const float*)d_in[3];
    float* out = (float*)d_out;
    int B = in_sizes[0] / 784;
    prep_kernel<<<6, 512>>>(w1, w2, wf);
    ring_kernel<<<B / 2, 320>>>(x, out);
}

// round 12
// speedup vs baseline: 1.2205x; 1.2205x over previous
#include <cuda_runtime.h>

typedef unsigned long long ull;

// Weight tables. Quads are (c, s, s, c):
//   ffma2(S, A, quad.lo): (vc*wc, vs*ws) -> Sx = lo+hi
//   ffma2(T, A, quad.hi): (vc*ws, vs*wc) -> Sy = hi-lo
__device__ __align__(16) float4 g_w1q[16];               // [co*4 + tap]
__device__ __align__(16) float g_w2c[544], g_w2s[544];   // [co*68 + c*16+i*4+j]
__device__ __align__(16) float4 g_wfq[2880];             // [o*288 + f]

__global__ void prep_kernel(const float* __restrict__ w1,
                            const float* __restrict__ w2,
                            const float* __restrict__ wf) {
    int gt = blockIdx.x * blockDim.x + threadIdx.x;
    for (int i = gt; i < 3408; i += gridDim.x * blockDim.x) {
        if (i < 16) {
            float s, c; sincosf(w1[i], &s, &c);
            g_w1q[i] = make_float4(c, s, s, c);
        } else if (i < 528) {
            int k = i - 16;
            int co = k >> 6, r = k & 63;
            float s, c; sincosf(w2[k], &s, &c);
            g_w2c[co * 68 + r] = c; g_w2s[co * 68 + r] = s;
        } else {
            int k = i - 528;
            int f = k / 10, o = k % 10;
            float s, c; sincosf(wf[k], &s, &c);
            g_wfq[o * 288 + f] = make_float4(c, s, s, c);
        }
    }
}

// packed dual-FMA: acc(lo,hi) += a(lo,hi) * b(lo,hi)
static __device__ __forceinline__ void ffma2(ull& acc, ull a, ull b) {
    asm("fma.rn.f32x2 %0, %1, %2, %0;" : "+l"(acc) : "l"(a), "l"(b));
}
static __device__ __forceinline__ float f2lo(ull v) { return __uint_as_float((unsigned)v); }
static __device__ __forceinline__ float f2hi(ull v) { return __uint_as_float((unsigned)(v >> 32)); }

// single-instruction MUFU rsqrt (MUFU pipe is idle in this kernel)
static __device__ __forceinline__ float mufu_rsqrt(float d) {
    float r;
    asm("rsqrt.approx.f32 %0, %1;" : "=f"(r) : "f"(d));
    return r;
}

// h1 arena (floats), bank phases so even-wo (A) and odd-wo (B) LDS.128 groups
// never share banks: cA@0 (bank0), cB@912 (bank16), sA@1808 (bank16), sB@2720 (bank0).
// Pads absorb B-copy underflow writes.
#define OFF_CA 0
#define OFF_CB 912
#define OFF_SA 1808
#define OFF_SB 2720
#define H1_TOTAL 3616

__global__ __launch_bounds__(320, 4) void ring_kernel(const float* __restrict__ x,
                                                      float* __restrict__ out) {
    __shared__ __align__(16) float2 s_px[784];          // interleaved (c,s) pixels
    __shared__ __align__(16) float s_h1[H1_TOTAL];
    __shared__ __align__(16) float2 s_h2[288];          // [(ho*6+wo)*8 + co]
    __shared__ __align__(16) float s_w2c[544], s_w2s[544];

    const int tid = threadIdx.x;

    // ---- w2 staging (consumed by stage 2, after 2 barriers) ----
    for (int i = tid; i < 544; i += 320) { s_w2c[i] = g_w2c[i]; s_w2s[i] = g_w2s[i]; }

    // ---- Stage 0: 784 sincos spread over ALL 10 warps (MUFU pipe) ----
    const float4* xb4 = reinterpret_cast<const float4*>(x + (size_t)blockIdx.x * 784);
    float4* px4 = reinterpret_cast<float4*>(s_px);
    for (int i = tid; i < 196; i += 320) {
        float4 v = xb4[i];
        float s0, c0, s1, c1, s2, c2, s3, c3;
        __sincosf(v.x, &s0, &c0);
        __sincosf(v.y, &s1, &c1);
        __sincosf(v.z, &s2, &c2);
        __sincosf(v.w, &s3, &c3);
        px4[2 * i]     = make_float4(c0, s0, c1, s1);
        px4[2 * i + 1] = make_float4(c2, s2, c3, s3);
    }
    __syncthreads();

    // ---- Stage 1: conv1 2x2 s2 -> 14x14x4; 196 threads, 4 co each ----
    if (tid < 196) {
        int py = tid / 14, px = tid % 14;
        int base = py * 56 + px * 2;                    // even -> 16B aligned
        ulonglong2 P0 = *(const ulonglong2*)&s_px[base];       // (A0, A1)
        ulonglong2 P1 = *(const ulonglong2*)&s_px[base + 28];  // (A2, A3)
        int dst = py * 16 + px;
        const ulonglong2* w1 = reinterpret_cast<const ulonglong2*>(g_w1q);
#pragma unroll
        for (int co = 0; co < 4; co++) {
            ulonglong2 q0 = __ldg(w1 + co * 4 + 0);
            ulonglong2 q1 = __ldg(w1 + co * 4 + 1);
            ulonglong2 q2 = __ldg(w1 + co * 4 + 2);
            ulonglong2 q3 = __ldg(w1 + co * 4 + 3);
            ull S = 0, T = 0;
            ffma2(S, P0.x, q0.x); ffma2(T, P0.x, q0.y);
            ffma2(S, P0.y, q1.x); ffma2(T, P0.y, q1.y);
            ffma2(S, P1.x, q2.x); ffma2(T, P1.x, q2.y);
            ffma2(S, P1.y, q3.x); ffma2(T, P1.y, q3.y);
            float Sx = f2lo(S) + f2hi(S);
            float Sy = f2hi(T) - f2lo(T);
            float r = mufu_rsqrt(fmaxf(Sx * Sx + Sy * Sy, 1e-30f));
            float hc = Sx * r, hs = Sy * r;
            int d = co * 224 + dst;
            s_h1[OFF_CA + d] = hc;
            s_h1[OFF_SA + d] = hs;
            s_h1[OFF_CB + d - 2] = hc;   // px<2 underflow lands in pads
            s_h1[OFF_SB + d - 2] = hs;
        }
    }
    __syncthreads();

    // ---- Stage 2: conv2 4x4 s2 -> 288 outputs; one/thread, all LDS.128 ----
    int st = tid + ((blockIdx.x & 3) << 5);   // rotate idle warp across SMSPs
    if (st >= 320) st -= 320;
    if (st < 288) {
        int co = st & 7, sp = st >> 3;        // co fastest -> broadcast in 8-lane groups
        int ho = sp / 6, wo = sp % 6;
        const float* pc = s_h1 + ((wo & 1) ? OFF_CB : OFF_CA);
        const float* ps = s_h1 + ((wo & 1) ? OFF_SB : OFF_SA);
        const int vb0 = ho * 32 + (wo & ~1) * 2;   // 16B-aligned window start
        const int wb0 = co * 68;
        ull S = 0, T3 = 0, T4 = 0;
#pragma unroll
        for (int c = 0; c < 4; c++) {
#pragma unroll
            for (int i = 0; i < 4; i++) {
                int vb = c * 224 + vb0 + i * 16;
                ulonglong2 vc = *(const ulonglong2*)&pc[vb];
                ulonglong2 vs = *(const ulonglong2*)&ps[vb];
                int wb = wb0 + c * 16 + i * 4;
                ulonglong2 wc = *(const ulonglong2*)&s_w2c[wb];
                ulonglong2 ws = *(const ulonglong2*)&s_w2s[wb];
                ffma2(S,  vc.x, wc.x); ffma2(S,  vc.y, wc.y);
                ffma2(S,  vs.x, ws.x); ffma2(S,  vs.y, ws.y);
                ffma2(T3, vs.x, wc.x); ffma2(T3, vs.y, wc.y);
                ffma2(T4, vc.x, ws.x); ffma2(T4, vc.y, ws.y);
            }
        }
        float Sx = f2lo(S) + f2hi(S);
        float Sy = (f2lo(T3) + f2hi(T3)) - (f2lo(T4) + f2hi(T4));
        float r = mufu_rsqrt(fmaxf(Sx * Sx + Sy * Sy, 1e-30f));
        s_h2[st] = make_float2(Sx * r, Sy * r);
    }
    __syncthreads();

    // ---- Stage 3: FF ring, one warp per class; wf quads from global (L1-hot) ----
    int o = tid >> 5, lane = tid & 31;
    const ulonglong2* wfo = reinterpret_cast<const ulonglong2*>(g_wfq + o * 288);
    ull S = 0, T = 0;
#pragma unroll
    for (int f = lane, k = 0; k < 9; k++, f += 32) {
        ull a = *(const ull*)&s_h2[f];
        ulonglong2 w = __ldg(wfo + f);
        ffma2(S, a, w.x);   // (c*wc, s*ws)
        ffma2(T, a, w.y);   // (c*ws, s*wc)
    }
    float Sx = f2lo(S) + f2hi(S);
    float Sy = f2hi(T) - f2lo(T);
#pragma unroll
    for (int off = 16; off; off >>= 1) {
        Sx += __shfl_xor_sync(0xffffffff, Sx, off);
        Sy += __shfl_xor_sync(0xffffffff, Sy, off);
    }
    if (lane == 0)
        out[(size_t)blockIdx.x * 10 + o] = Sy * mufu_rsqrt(fmaxf(Sx * Sx + Sy * Sy, 1e-30f));
}

extern "C" void kernel_launch(void* const* d_in, const int* in_sizes, int n_in,
                              void* d_out, int out_size) {
    const float* x  = (const float*)d_in[0];
    const float* w1 = (const float*)d_in[1];
    const float* w2 = (const float*)d_in[2];
    const float* wf = (const float*)d_in[3];
    float* out = (float*)d_out;
    int B = in_sizes[0] / 784;
    prep_kernel<<<6, 512>>>(w1, w2, wf);
    ring_kernel<<<B, 320>>>(x, out);
}

// round 13
// speedup vs baseline: 1.5070x; 1.2347x over previous
#include <cuda_runtime.h>

typedef unsigned long long ull;

// ---- SoA weight planes + quad FF table ----
__device__ __align__(16) float g_w1c[16],  g_w1s[16];    // [co*4 + i*2 + j]
__device__ __align__(16) float g_w2c[544], g_w2s[544];   // [co*68 + c*16+i*4+j]
__device__ __align__(16) float4 g_wfq[2880];             // [o*288 + f] = (c,s,s,c)

__global__ void prep_kernel(const float* __restrict__ w1,
                            const float* __restrict__ w2,
                            const float* __restrict__ wf) {
    int gt = blockIdx.x * blockDim.x + threadIdx.x;
    for (int i = gt; i < 3408; i += gridDim.x * blockDim.x) {
        if (i < 16) {
            float s, c; sincosf(w1[i], &s, &c);
            g_w1c[i] = c; g_w1s[i] = s;
        } else if (i < 528) {
            int k = i - 16;
            int co = k >> 6, r = k & 63;
            float s, c; sincosf(w2[k], &s, &c);
            g_w2c[co * 68 + r] = c; g_w2s[co * 68 + r] = s;
        } else {
            int k = i - 528;
            int f = k / 10, o = k % 10;
            float s, c; sincosf(wf[k], &s, &c);
            g_wfq[o * 288 + f] = make_float4(c, s, s, c);
        }
    }
}

// packed dual-FMA: acc(lo,hi) += a(lo,hi) * b(lo,hi)
static __device__ __forceinline__ void ffma2(ull& acc, ull a, ull b) {
    asm("fma.rn.f32x2 %0, %1, %2, %0;" : "+l"(acc) : "l"(a), "l"(b));
}
static __device__ __forceinline__ float f2lo(ull v) { return __uint_as_float((unsigned)v); }
static __device__ __forceinline__ float f2hi(ull v) { return __uint_as_float((unsigned)(v >> 32)); }

// FMA-pipe sincos (R4-proven: beats MUFU bursts for bulk pixel trig)
static __device__ __forceinline__ void fast_sincos(float x, float& s, float& c) {
    float t = fmaf(x, 0.63661977236758134f, 12582912.0f);
    unsigned q = __float_as_uint(t);
    float kf = t - 12582912.0f;
    float r = fmaf(kf, -1.57079625129699707031f, x);
    r = fmaf(kf, -7.54978941586159e-08f, r);
    float y = r * r;
    float ps = fmaf(y, -1.95152959e-4f, 8.33216087e-3f);
    ps = fmaf(y, ps, -1.66666546e-1f);
    float s0 = fmaf(r * y, ps, r);
    float pc = fmaf(y, 2.44331571e-5f, -1.38873162e-3f);
    pc = fmaf(y, pc, 4.16666232e-2f);
    pc = fmaf(y, pc, -0.5f);
    float c0 = fmaf(y, pc, 1.0f);
    bool sw = q & 1u;
    float ss = sw ? c0 : s0;
    float cc = sw ? s0 : c0;
    unsigned sgs = (q & 2u) << 30;
    unsigned sgc = ((q + 1u) & 2u) << 30;
    s = __uint_as_float(__float_as_uint(ss) ^ sgs);
    c = __uint_as_float(__float_as_uint(cc) ^ sgc);
}

// single-instruction MUFU rsqrt (amortized use, MUFU pipe idle)
static __device__ __forceinline__ float mufu_rsqrt(float d) {
    float r;
    asm("rsqrt.approx.f32 %0, %1;" : "=f"(r) : "f"(d));
    return r;
}

__global__ __launch_bounds__(320, 4) void ring_kernel(const float* __restrict__ x,
                                                      float* __restrict__ out) {
    __shared__ __align__(16) float s_pxc[784], s_pxs[784];   // pixel planes 28x28
    __shared__ __align__(16) float s_h1c[896], s_h1s[896];   // [co*224 + py*16 + px]
    __shared__ __align__(16) float2 s_h2[288];               // [(ho*6+wo)*8 + co]
    __shared__ __align__(16) float s_w1c[16],  s_w1s[16];
    __shared__ __align__(16) float s_w2c[544], s_w2s[544];

    const int tid = threadIdx.x;

    // ---- Stage 0: pixel trig (poly, FMA pipe) + weight staging ----
    const float4* xb4 = reinterpret_cast<const float4*>(x + (size_t)blockIdx.x * 784);
    for (int i = tid; i < 196; i += 320) {
        float4 v = xb4[i];
        float s0, c0, s1, c1, s2, c2, s3, c3;
        fast_sincos(v.x, s0, c0);
        fast_sincos(v.y, s1, c1);
        fast_sincos(v.z, s2, c2);
        fast_sincos(v.w, s3, c3);
        *reinterpret_cast<float4*>(&s_pxc[4 * i]) = make_float4(c0, c1, c2, c3);
        *reinterpret_cast<float4*>(&s_pxs[4 * i]) = make_float4(s0, s1, s2, s3);
    }
    if (tid < 16) { s_w1c[tid] = g_w1c[tid]; s_w1s[tid] = g_w1s[tid]; }
    for (int i = tid; i < 544; i += 320) { s_w2c[i] = g_w2c[i]; s_w2s[i] = g_w2s[i]; }
    __syncthreads();

    // ---- Stage 1: conv1 2x2 s2 -> 14x14x4; one spatial pos/thread, 4 co ----
    if (tid < 196) {
        int py = tid / 14, px = tid % 14;
        int base = py * 56 + px * 2;
        ull vc0 = *(const ull*)&s_pxc[base];
        ull vc1 = *(const ull*)&s_pxc[base + 28];
        ull vs0 = *(const ull*)&s_pxs[base];
        ull vs1 = *(const ull*)&s_pxs[base + 28];
        int dst = py * 16 + px;
#pragma unroll
        for (int co = 0; co < 4; co++) {
            ulonglong2 wc = *(const ulonglong2*)&s_w1c[co * 4];
            ulonglong2 ws = *(const ulonglong2*)&s_w1s[co * 4];
            ull S = 0, T3 = 0, T4 = 0;
            ffma2(S,  vc0, wc.x); ffma2(S,  vc1, wc.y);
            ffma2(S,  vs0, ws.x); ffma2(S,  vs1, ws.y);
            ffma2(T3, vs0, wc.x); ffma2(T3, vs1, wc.y);
            ffma2(T4, vc0, ws.x); ffma2(T4, vc1, ws.y);
            float Sx = f2lo(S) + f2hi(S);
            float Sy = (f2lo(T3) + f2hi(T3)) - (f2lo(T4) + f2hi(T4));
            float r = mufu_rsqrt(fmaxf(Sx * Sx + Sy * Sy, 1e-30f));
            int d = co * 224 + dst;
            s_h1c[d] = Sx * r;
            s_h1s[d] = Sy * r;
        }
    }
    __syncthreads();

    // ---- Stage 2: conv2 4x4 s2 -> 288 outputs; 144 threads x 2 outputs (R4) ----
    int st = tid + ((blockIdx.x & 3) << 5);   // rotate active window across SMSPs
    if (st >= 320) st -= 320;
    if (st < 144) {
        int co = st & 7, q = st >> 3;          // co fastest -> v broadcast in 8-lane groups
        int ho = q / 3, wp = q % 3;            // outputs wo = 2wp, 2wp+1
        const int vb0 = ho * 32 + wp * 4;
        const int wb0 = co * 68;
        ull SA = 0, TA3 = 0, TA4 = 0, SB = 0, TB3 = 0, TB4 = 0;
#pragma unroll
        for (int c = 0; c < 4; c++) {
#pragma unroll
            for (int i = 0; i < 4; i++) {
                int vb = c * 224 + vb0 + i * 16;
                ull vc0 = *(const ull*)&s_h1c[vb];
                ull vc1 = *(const ull*)&s_h1c[vb + 2];
                ull vc2 = *(const ull*)&s_h1c[vb + 4];
                ull vs0 = *(const ull*)&s_h1s[vb];
                ull vs1 = *(const ull*)&s_h1s[vb + 2];
                ull vs2 = *(const ull*)&s_h1s[vb + 4];
                int wb = wb0 + c * 16 + i * 4;
                ulonglong2 wc = *(const ulonglong2*)&s_w2c[wb];
                ulonglong2 ws = *(const ulonglong2*)&s_w2s[wb];
                // output A: px 0..3
                ffma2(SA,  vc0, wc.x); ffma2(SA,  vc1, wc.y);
                ffma2(SA,  vs0, ws.x); ffma2(SA,  vs1, ws.y);
                ffma2(TA3, vs0, wc.x); ffma2(TA3, vs1, wc.y);
                ffma2(TA4, vc0, ws.x); ffma2(TA4, vc1, ws.y);
                // output B: px 2..5
                ffma2(SB,  vc1, wc.x); ffma2(SB,  vc2, wc.y);
                ffma2(SB,  vs1, ws.x); ffma2(SB,  vs2, ws.y);
                ffma2(TB3, vs1, wc.x); ffma2(TB3, vs2, wc.y);
                ffma2(TB4, vc1, ws.x); ffma2(TB4, vc2, ws.y);
            }
        }
        int d0 = (ho * 6 + 2 * wp) * 8 + co;
        {
            float Sx = f2lo(SA) + f2hi(SA);
            float Sy = (f2lo(TA3) + f2hi(TA3)) - (f2lo(TA4) + f2hi(TA4));
            float r = mufu_rsqrt(fmaxf(Sx * Sx + Sy * Sy, 1e-30f));
            s_h2[d0] = make_float2(Sx * r, Sy * r);
        }
        {
            float Sx = f2lo(SB) + f2hi(SB);
            float Sy = (f2lo(TB3) + f2hi(TB3)) - (f2lo(TB4) + f2hi(TB4));
            float r = mufu_rsqrt(fmaxf(Sx * Sx + Sy * Sy, 1e-30f));
            s_h2[d0 + 8] = make_float2(Sx * r, Sy * r);
        }
    }
    __syncthreads();

    // ---- Stage 3: FF ring, one warp per class; quad taps, 1 LDG.128 each ----
    int o = tid >> 5, lane = tid & 31;
    const ulonglong2* wfo = reinterpret_cast<const ulonglong2*>(g_wfq + o * 288);
    ull S = 0, T = 0;
#pragma unroll
    for (int f = lane, k = 0; k < 9; k++, f += 32) {
        ull a = *(const ull*)&s_h2[f];
        ulonglong2 w = __ldg(wfo + f);
        ffma2(S, a, w.x);   // (c*wc, s*ws) -> Sx = lo+hi
        ffma2(T, a, w.y);   // (c*ws, s*wc) -> Sy = hi-lo
    }
    float Sx = f2lo(S) + f2hi(S);
    float Sy = f2hi(T) - f2lo(T);
#pragma unroll
    for (int off = 16; off; off >>= 1) {
        Sx += __shfl_xor_sync(0xffffffff, Sx, off);
        Sy += __shfl_xor_sync(0xffffffff, Sy, off);
    }
    if (lane == 0)
        out[(size_t)blockIdx.x * 10 + o] = Sy * mufu_rsqrt(fmaxf(Sx * Sx + Sy * Sy, 1e-30f));
}

extern "C" void kernel_launch(void* const* d_in, const int* in_sizes, int n_in,
                              void* d_out, int out_size) {
    const float* x  = (const float*)d_in[0];
    const float* w1 = (const float*)d_in[1];
    const float* w2 = (const float*)d_in[2];
    const float* wf = (const float*)d_in[3];
    float* out = (float*)d_out;
    int B = in_sizes[0] / 784;
    prep_kernel<<<6, 512>>>(w1, w2, wf);
    ring_kernel<<<B, 320>>>(x, out);
}